// round 7
// baseline (speedup 1.0000x reference)
#include <cuda_runtime.h>
#include <cuda_bf16.h>
#include <cuda_fp16.h>
#include <cstdint>
#include <math.h>

// NT-Xent loss, N=4096, D=256, T=0.5. FP8 e4m3 mma.sync (m16n8k32, QMMA),
// upper-triangle symmetric, mbarrier-pipelined persistent kernel.
// denom_k = sum_{j!=k} exp(2*sim_kj) with sim via fp8 GEMM (fp32 accum);
// pos_k fp32-exact; diagonal removed exactly via exp(2*sum(fp8(z_k)^2)).

#define NROW 8192
#define NHALF 4096
#define DIM 256
#define NTILE 64
#define TOTAL_UT 2080               // 64*65/2
#define C2 2.885390081777927f       // 2 * log2(e)

// smem: fp8 tiles 128x256 = 32KB each, 256B rows, XOR-16B-chunk swizzle
#define SM_A 0
#define SM_B0 32768
#define SM_B1 65536
#define SM_BAR 98304
#define SMEM_TOTAL (98304 + 64)

__device__ unsigned char g_z8[NROW * DIM];   // e4m3 normalized rows (2 MB)
__device__ float g_denom[NROW];
__device__ float g_pos[NHALF];
__device__ float g_self[NROW];               // sum(fp8(z)^2), fp32

// ---------------------------------------------------------------------------
__device__ __forceinline__ float ex2f(float x) {
    float y; asm("ex2.approx.ftz.f32 %0, %1;" : "=f"(y) : "f"(x)); return y;
}
__device__ __forceinline__ uint32_t smem_u32(const void* p) {
    uint32_t a;
    asm("{ .reg .u64 t; cvta.to.shared.u64 t, %1; cvt.u32.u64 %0, t; }"
        : "=r"(a) : "l"(p));
    return a;
}
__device__ __forceinline__ void cp16(uint32_t s, const void* g) {
    asm volatile("cp.async.cg.shared.global [%0], [%1], 16;" :: "r"(s), "l"(g));
}
#define CP_COMMIT() asm volatile("cp.async.commit_group;" ::: "memory")
#define CP_WAIT0()  asm volatile("cp.async.wait_group 0;" ::: "memory")

#define MBAR_INIT(a, c) \
    asm volatile("mbarrier.init.shared.b64 [%0], %1;" :: "r"(a), "r"(c) : "memory")
#define MBAR_INVAL(a) \
    asm volatile("mbarrier.inval.shared.b64 [%0];" :: "r"(a) : "memory")
#define MBAR_ARRIVE(a) \
    asm volatile("mbarrier.arrive.shared.b64 _, [%0];" :: "r"(a) : "memory")
#define CPA_NOINC(a) \
    asm volatile("cp.async.mbarrier.arrive.noinc.shared.b64 [%0];" :: "r"(a) : "memory")

#define MBAR_WAIT(mbar, ph) do {                                              \
    uint32_t _m = (mbar); uint32_t _p = (uint32_t)(ph); uint32_t _done;       \
    asm volatile("{\n\t.reg .pred p;\n\t"                                     \
        "mbarrier.try_wait.parity.shared.b64 p, [%1], %2;\n\t"                \
        "selp.b32 %0, 1, 0, p;\n\t}"                                          \
        : "=r"(_done) : "r"(_m), "r"(_p) : "memory");                         \
    if (!_done) {                                                             \
        asm volatile("{\n\t.reg .pred P1;\n\t"                                \
            "WL_%=:\n\t"                                                      \
            "mbarrier.try_wait.parity.shared.b64 P1, [%0], %1;\n\t"           \
            "@P1 bra.uni WD_%=;\n\t"                                          \
            "bra.uni WL_%=;\n\t"                                              \
            "WD_%=:\n\t}" :: "r"(_m), "r"(_p) : "memory");                    \
    }                                                                         \
} while (0)

#define LDSM4(r0, r1, r2, r3, a)                                        \
    asm volatile("ldmatrix.sync.aligned.m8n8.x4.shared.b16 "            \
                 "{%0,%1,%2,%3}, [%4];"                                 \
                 : "=r"(r0), "=r"(r1), "=r"(r2), "=r"(r3) : "r"(a))

#define MMA16832(c, a, b0, b1)                                          \
    asm volatile("mma.sync.aligned.m16n8k32.row.col.f32.e4m3.e4m3.f32 "\
                 "{%0,%1,%2,%3}, {%4,%5,%6,%7}, {%8,%9}, {%0,%1,%2,%3};"\
                 : "+f"((c)[0]), "+f"((c)[1]), "+f"((c)[2]), "+f"((c)[3]) \
                 : "r"((a)[0]), "r"((a)[1]), "r"((a)[2]), "r"((a)[3]),  \
                   "r"(b0), "r"(b1))

// ---------------------------------------------------------------------------
// Kernel 1: normalize (warp per row); fp8 z, fp8 self-sim, fp32 positives.
// grid = 1024 x 256.
// ---------------------------------------------------------------------------
__global__ void norm_pos_kernel(const float* __restrict__ ei,
                                const float* __restrict__ ej) {
    const int tid = threadIdx.x, w = tid >> 5, lane = tid & 31;
    const int half = w >> 2;
    const int k = blockIdx.x * 4 + (w & 3);
    const int row = k + half * NHALF;
    const float* src = (half ? ej : ei) + (size_t)k * DIM + lane * 8;

    float4 v0 = *reinterpret_cast<const float4*>(src);
    float4 v1 = *reinterpret_cast<const float4*>(src + 4);
    float vf[8] = {v0.x, v0.y, v0.z, v0.w, v1.x, v1.y, v1.z, v1.w};

    float s = 0.f;
    #pragma unroll
    for (int i = 0; i < 8; i++) s += vf[i] * vf[i];
    #pragma unroll
    for (int o = 16; o; o >>= 1) s += __shfl_xor_sync(~0u, s, o);
    const float inv = 1.0f / fmaxf(sqrtf(s), 1e-8f);

    float zf[8];
    #pragma unroll
    for (int i = 0; i < 8; i++) zf[i] = vf[i] * inv;

    // fp32 -> e4m3 (packed pairs) + exact roundtrip for self-sim
    uint16_t pk[4];
    float ss = 0.f;
    #pragma unroll
    for (int i = 0; i < 4; i++) {
        asm("cvt.rn.satfinite.e4m3x2.f32 %0, %1, %2;"
            : "=h"(pk[i]) : "f"(zf[2 * i + 1]), "f"(zf[2 * i]));
        uint32_t h2;
        asm("cvt.rn.f16x2.e4m3x2 %0, %1;" : "=r"(h2) : "h"(pk[i]));
        __half2 hh = *reinterpret_cast<__half2*>(&h2);
        float lo = __half2float(hh.x), hi = __half2float(hh.y);
        ss += lo * lo + hi * hi;
    }
    uint2 packed;
    packed.x = (uint32_t)pk[0] | ((uint32_t)pk[1] << 16);
    packed.y = (uint32_t)pk[2] | ((uint32_t)pk[3] << 16);
    *reinterpret_cast<uint2*>(&g_z8[(size_t)row * DIM + lane * 8]) = packed;

    #pragma unroll
    for (int o = 16; o; o >>= 1) ss += __shfl_xor_sync(~0u, ss, o);
    if (lane == 0) { g_self[row] = ss; g_denom[row] = 0.f; }

    // positive pair dot (fp32 exact, matches reference)
    __shared__ float zsh[4][DIM];
    if (half == 0) {
        #pragma unroll
        for (int i = 0; i < 8; i++) zsh[w & 3][lane * 8 + i] = zf[i];
    }
    __syncthreads();
    if (half == 1) {
        float p = 0.f;
        #pragma unroll
        for (int i = 0; i < 8; i++) p += zsh[w & 3][lane * 8 + i] * zf[i];
        #pragma unroll
        for (int o = 16; o; o >>= 1) p += __shfl_xor_sync(~0u, p, o);
        if (lane == 0) g_pos[k] = p;
    }
}

// ---------------------------------------------------------------------------
// cp.async of a 128x256 fp8 tile into 256B-row smem, 16B-chunk XOR swizzle
// (chunk c of row r stored at c ^ (r&7); c in 0..15). No commit here.
// ---------------------------------------------------------------------------
__device__ __forceinline__ void fill_tile(uint32_t sdst, int zrow, int tid) {
    const unsigned char* src = g_z8 + ((size_t)zrow << 8);
    #pragma unroll
    for (int i = 0; i < 8; ++i) {
        int q = tid + (i << 8);          // 16B chunk id 0..2047
        int r = q >> 4;                  // row 0..127
        int c = q & 15;                  // chunk in row
        cp16(sdst + (r << 8) + ((c ^ (r & 7)) << 4), src + ((size_t)q << 4));
    }
}

// ---------------------------------------------------------------------------
// Kernel 2: persistent upper-tri fp8 sim-GEMM + exp-sum, mbarrier-pipelined.
// 148 CTAs x 256 threads; 8 warps = 2(M) x 4(N); warp tile 64x32.
// ---------------------------------------------------------------------------
__global__ __launch_bounds__(256, 1) void sim_kernel() {
    extern __shared__ char smem[];
    const uint32_t sb = smem_u32(smem);
    const uint32_t FULL[2]  = {sb + SM_BAR,      sb + SM_BAR + 8};
    const uint32_t EMPTY[2] = {sb + SM_BAR + 16, sb + SM_BAR + 24};
    const uint32_t BUF[2]   = {sb + SM_B0, sb + SM_B1};
    const int tid = threadIdx.x, wid = tid >> 5, lane = tid & 31;
    const int wm = wid >> 2, wn = wid & 3;

    const int b = blockIdx.x, nb = gridDim.x;
    const int t0 = (b * TOTAL_UT) / nb;
    const int t1 = ((b + 1) * TOTAL_UT) / nb;
    const int nt = t1 - t0;
    if (nt <= 0) return;

    int R = 0, rem = t0;
    while (rem >= NTILE - R) { rem -= NTILE - R; R++; }
    int C = R + rem;

    if (tid == 0) {
        MBAR_INIT(FULL[0], 256); MBAR_INIT(FULL[1], 256);
        MBAR_INIT(EMPTY[0], 256); MBAR_INIT(EMPTY[1], 256);
    }
    __syncthreads();

    // ldmatrix per-lane addressing (rows are 256B; swizzle mask = lane&7)
    const int rA = (lane & 7) + (((lane >> 3) & 1) << 3);  // fragment row 0..15
    const uint32_t hi = (uint32_t)(lane >> 4);             // chunk parity
    const uint32_t rm = (uint32_t)(lane & 7);              // XOR mask
    uint32_t aRow[4], bRow[2];
    #pragma unroll
    for (int mf = 0; mf < 4; ++mf)
        aRow[mf] = (uint32_t)(wm * 64 + mf * 16 + rA) << 8;
    #pragma unroll
    for (int g = 0; g < 2; ++g)
        bRow[g] = (uint32_t)(wn * 32 + g * 16 + rA) << 8;

    float dacc[4][2];
    #pragma unroll
    for (int i = 0; i < 4; i++) { dacc[i][0] = 0.f; dacc[i][1] = 0.f; }

    int loadedR = R;
    fill_tile(sb + SM_A, R << 7, tid);
    fill_tile(BUF[0], C << 7, tid);
    CPA_NOINC(FULL[0]);
    CP_COMMIT(); CP_WAIT0();
    __syncthreads();                     // A (and fill0) visible to all

    for (int i = 0; i < nt; ++i) {
        int Rn = R, Cn = C + 1;
        if (Cn == NTILE) { Rn = R + 1; Cn = Rn; }

        if (R != loadedR) {              // rare: flush rows + reload A
            #pragma unroll
            for (int mf = 0; mf < 4; ++mf)
                #pragma unroll
                for (int h = 0; h < 2; ++h) {
                    float v = dacc[mf][h];
                    v += __shfl_xor_sync(~0u, v, 1);
                    v += __shfl_xor_sync(~0u, v, 2);
                    if ((lane & 3) == 0)
                        atomicAdd(&g_denom[(loadedR << 7) + wm * 64 + mf * 16
                                           + (lane >> 2) + h * 8], v);
                    dacc[mf][h] = 0.f;
                }
            __syncthreads();
            fill_tile(sb + SM_A, R << 7, tid);
            CP_COMMIT(); CP_WAIT0();
            __syncthreads();
            loadedR = R;
        }

        // prefetch tile i+1 into the other buffer
        if (i + 1 < nt) {
            const int nbuf = (i + 1) & 1;
            if (i + 1 >= 2)
                MBAR_WAIT(EMPTY[nbuf], ((((i + 1) >> 1) - 1) & 1));
            fill_tile(BUF[nbuf], Cn << 7, tid);
            CPA_NOINC(FULL[nbuf]);
        }

        // consume tile i
        const int cb = i & 1;
        MBAR_WAIT(FULL[cb], (i >> 1) & 1);
        const uint32_t aBase = sb + SM_A;
        const uint32_t bBase = BUF[cb];

        float acc[4][4][4];
        #pragma unroll
        for (int x = 0; x < 4; x++)
            #pragma unroll
            for (int y = 0; y < 4; y++)
                #pragma unroll
                for (int c = 0; c < 4; c++) acc[x][y][c] = 0.f;

        #pragma unroll
        for (int s = 0; s < 8; ++s) {    // 8 k-steps of 32 fp8
            const uint32_t off = ((((uint32_t)s << 1) + hi) ^ rm) << 4;
            uint32_t a[4][4];
            #pragma unroll
            for (int mf = 0; mf < 4; ++mf)
                LDSM4(a[mf][0], a[mf][1], a[mf][2], a[mf][3],
                      aBase + aRow[mf] + off);
            uint32_t bq[2][4];
            #pragma unroll
            for (int g = 0; g < 2; ++g)
                LDSM4(bq[g][0], bq[g][1], bq[g][2], bq[g][3],
                      bBase + bRow[g] + off);
            #pragma unroll
            for (int mf = 0; mf < 4; ++mf)
                #pragma unroll
                for (int nf = 0; nf < 4; ++nf)
                    MMA16832(acc[mf][nf], a[mf],
                             bq[nf >> 1][nf & 1],
                             bq[nf >> 1][(nf & 1) + 2]);
        }
        MBAR_ARRIVE(EMPTY[cb]);          // done reading this B buffer

        // epilogue (overlaps other warps' MMA)
        const bool offDiag = (C != R);
        float colacc[4][2];
        #pragma unroll
        for (int x = 0; x < 4; x++) { colacc[x][0] = 0.f; colacc[x][1] = 0.f; }

        #pragma unroll
        for (int mf = 0; mf < 4; ++mf)
            #pragma unroll
            for (int nf = 0; nf < 4; ++nf)
                #pragma unroll
                for (int c = 0; c < 4; ++c) {
                    float e = ex2f(acc[mf][nf][c] * C2);
                    dacc[mf][c >> 1] += e;
                    colacc[nf][c & 1] += e;
                }

        if (offDiag) {
            #pragma unroll
            for (int nf = 0; nf < 4; ++nf)
                #pragma unroll
                for (int p = 0; p < 2; ++p) {
                    float v = colacc[nf][p];
                    v += __shfl_xor_sync(~0u, v, 4);
                    v += __shfl_xor_sync(~0u, v, 8);
                    v += __shfl_xor_sync(~0u, v, 16);
                    if (lane < 4)
                        atomicAdd(&g_denom[(C << 7) + wn * 32 + nf * 8
                                           + (lane & 3) * 2 + p], v);
                }
        }

        R = Rn; C = Cn;
    }

    // final row flush
    #pragma unroll
    for (int mf = 0; mf < 4; ++mf)
        #pragma unroll
        for (int h = 0; h < 2; ++h) {
            float v = dacc[mf][h];
            v += __shfl_xor_sync(~0u, v, 1);
            v += __shfl_xor_sync(~0u, v, 2);
            if ((lane & 3) == 0)
                atomicAdd(&g_denom[(loadedR << 7) + wm * 64 + mf * 16
                                   + (lane >> 2) + h * 8], v);
        }

    __syncthreads();
    if (tid == 0) {
        MBAR_INVAL(FULL[0]); MBAR_INVAL(FULL[1]);
        MBAR_INVAL(EMPTY[0]); MBAR_INVAL(EMPTY[1]);
    }
}

// ---------------------------------------------------------------------------
__global__ void finish_kernel(float* __restrict__ out) {
    int tid = threadIdx.x;
    double s = 0.0;
    for (int r = tid; r < NROW; r += 512) {
        float denom = g_denom[r] - ex2f(g_self[r] * C2);
        int pk = (r < NHALF) ? r : (r - NHALF);
        s += (double)(__logf(denom) - 2.0f * g_pos[pk]);
    }
    #pragma unroll
    for (int o = 16; o; o >>= 1) s += __shfl_xor_sync(~0u, s, o);
    __shared__ double ws[16];
    int lane = tid & 31, w = tid >> 5;
    if (lane == 0) ws[w] = s;
    __syncthreads();
    if (tid == 0) {
        double tot = 0.0;
        #pragma unroll
        for (int i = 0; i < 16; i++) tot += ws[i];
        out[0] = (float)(tot / (double)NROW);
    }
}

// ---------------------------------------------------------------------------
extern "C" void kernel_launch(void* const* d_in, const int* in_sizes, int n_in,
                              void* d_out, int out_size) {
    const float* emb_i = (const float*)d_in[0];
    const float* emb_j = (const float*)d_in[1];
    float* out = (float*)d_out;

    cudaFuncSetAttribute(sim_kernel, cudaFuncAttributeMaxDynamicSharedMemorySize,
                         SMEM_TOTAL);
    norm_pos_kernel<<<1024, 256>>>(emb_i, emb_j);
    sim_kernel<<<148, 256, SMEM_TOTAL>>>();
    finish_kernel<<<1, 512>>>(out);
}

// round 8
// speedup vs baseline: 1.0748x; 1.0748x over previous
#include <cuda_runtime.h>
#include <cuda_bf16.h>
#include <cstdint>
#include <math.h>

// NT-Xent loss, N=4096, D=256, T=0.5. bf16 mma.sync m16n8k16, upper-triangle
// symmetric, mbarrier-pipelined, 512-thread (16-warp) persistent kernel with
// fused final reduction (last CTA writes the scalar).

#define NROW 8192
#define NHALF 4096
#define DIM 256
#define NTILE 64
#define TOTAL_UT 2080               // 64*65/2
#define C2 2.885390081777927f       // 2 * log2(e)
#define NB 148

// smem: swizzled 512B-row bf16 tiles (64KB each): A + B0 + B1 + mbarriers
#define SM_A 0
#define SM_B0 65536
#define SM_B1 131072
#define SM_BAR 196608
#define SMEM_TOTAL (196608 + 64)

__device__ __nv_bfloat16 g_zh[NROW * DIM];
__device__ float g_denom[NROW];
__device__ float g_pos[NHALF];
__device__ float g_self[NROW];
__device__ unsigned int g_done;

// ---------------------------------------------------------------------------
__device__ __forceinline__ float ex2f(float x) {
    float y; asm("ex2.approx.ftz.f32 %0, %1;" : "=f"(y) : "f"(x)); return y;
}
__device__ __forceinline__ uint32_t smem_u32(const void* p) {
    uint32_t a;
    asm("{ .reg .u64 t; cvta.to.shared.u64 t, %1; cvt.u32.u64 %0, t; }"
        : "=r"(a) : "l"(p));
    return a;
}
__device__ __forceinline__ void cp16(uint32_t s, const void* g) {
    asm volatile("cp.async.cg.shared.global [%0], [%1], 16;" :: "r"(s), "l"(g));
}
#define CP_COMMIT() asm volatile("cp.async.commit_group;" ::: "memory")
#define CP_WAIT0()  asm volatile("cp.async.wait_group 0;" ::: "memory")

#define MBAR_INIT(a, c) \
    asm volatile("mbarrier.init.shared.b64 [%0], %1;" :: "r"(a), "r"(c) : "memory")
#define MBAR_INVAL(a) \
    asm volatile("mbarrier.inval.shared.b64 [%0];" :: "r"(a) : "memory")
#define MBAR_ARRIVE(a) \
    asm volatile("mbarrier.arrive.shared.b64 _, [%0];" :: "r"(a) : "memory")
#define CPA_NOINC(a) \
    asm volatile("cp.async.mbarrier.arrive.noinc.shared.b64 [%0];" :: "r"(a) : "memory")

#define MBAR_WAIT(mbar, ph) do {                                              \
    uint32_t _m = (mbar); uint32_t _p = (uint32_t)(ph); uint32_t _done;       \
    asm volatile("{\n\t.reg .pred p;\n\t"                                     \
        "mbarrier.try_wait.parity.shared.b64 p, [%1], %2;\n\t"                \
        "selp.b32 %0, 1, 0, p;\n\t}"                                          \
        : "=r"(_done) : "r"(_m), "r"(_p) : "memory");                         \
    if (!_done) {                                                             \
        asm volatile("{\n\t.reg .pred P1;\n\t"                                \
            "WL_%=:\n\t"                                                      \
            "mbarrier.try_wait.parity.shared.b64 P1, [%0], %1;\n\t"           \
            "@P1 bra.uni WD_%=;\n\t"                                          \
            "bra.uni WL_%=;\n\t"                                              \
            "WD_%=:\n\t}" :: "r"(_m), "r"(_p) : "memory");                    \
    }                                                                         \
} while (0)

#define LDSM4(r0, r1, r2, r3, a)                                        \
    asm volatile("ldmatrix.sync.aligned.m8n8.x4.shared.b16 "            \
                 "{%0,%1,%2,%3}, [%4];"                                 \
                 : "=r"(r0), "=r"(r1), "=r"(r2), "=r"(r3) : "r"(a))

#define MMA16816(c, a, b0, b1)                                          \
    asm volatile("mma.sync.aligned.m16n8k16.row.col.f32.bf16.bf16.f32 " \
                 "{%0,%1,%2,%3}, {%4,%5,%6,%7}, {%8,%9}, {%0,%1,%2,%3};"\
                 : "+f"((c)[0]), "+f"((c)[1]), "+f"((c)[2]), "+f"((c)[3]) \
                 : "r"((a)[0]), "r"((a)[1]), "r"((a)[2]), "r"((a)[3]),  \
                   "r"(b0), "r"(b1))

// ---------------------------------------------------------------------------
// Kernel 1: normalize (warp per row); bf16 z, self-sim, fp32 positives.
// grid = 1024 x 256.
// ---------------------------------------------------------------------------
__global__ void norm_pos_kernel(const float* __restrict__ ei,
                                const float* __restrict__ ej) {
    const int tid = threadIdx.x, w = tid >> 5, lane = tid & 31;
    const int half = w >> 2;
    const int k = blockIdx.x * 4 + (w & 3);
    const int row = k + half * NHALF;
    const float* src = (half ? ej : ei) + (size_t)k * DIM + lane * 8;

    if (blockIdx.x == 0 && tid == 0) g_done = 0;

    float4 v0 = *reinterpret_cast<const float4*>(src);
    float4 v1 = *reinterpret_cast<const float4*>(src + 4);
    float vf[8] = {v0.x, v0.y, v0.z, v0.w, v1.x, v1.y, v1.z, v1.w};

    float s = 0.f;
    #pragma unroll
    for (int i = 0; i < 8; i++) s += vf[i] * vf[i];
    #pragma unroll
    for (int o = 16; o; o >>= 1) s += __shfl_xor_sync(~0u, s, o);
    const float inv = 1.0f / fmaxf(sqrtf(s), 1e-8f);

    float zf[8];
    __nv_bfloat162 zb[4];
    float ss = 0.f;
    #pragma unroll
    for (int i = 0; i < 8; i++) zf[i] = vf[i] * inv;
    #pragma unroll
    for (int i = 0; i < 4; i++) {
        zb[i] = __floats2bfloat162_rn(zf[2 * i], zf[2 * i + 1]);
        float lo = __bfloat162float(zb[i].x), hi = __bfloat162float(zb[i].y);
        ss += lo * lo + hi * hi;
    }
    *reinterpret_cast<uint4*>(&g_zh[(size_t)row * DIM + lane * 8]) =
        *reinterpret_cast<uint4*>(zb);
    #pragma unroll
    for (int o = 16; o; o >>= 1) ss += __shfl_xor_sync(~0u, ss, o);
    if (lane == 0) { g_self[row] = ss; g_denom[row] = 0.f; }

    __shared__ float zsh[4][DIM];
    if (half == 0) {
        #pragma unroll
        for (int i = 0; i < 8; i++) zsh[w & 3][lane * 8 + i] = zf[i];
    }
    __syncthreads();
    if (half == 1) {
        float p = 0.f;
        #pragma unroll
        for (int i = 0; i < 8; i++) p += zsh[w & 3][lane * 8 + i] * zf[i];
        #pragma unroll
        for (int o = 16; o; o >>= 1) p += __shfl_xor_sync(~0u, p, o);
        if (lane == 0) g_pos[k] = p;
    }
}

// ---------------------------------------------------------------------------
// cp.async of a 128x256 bf16 tile into 512B-row smem, 16B-chunk XOR swizzle
// (chunk c of row r at c ^ (r&7)). 512 threads, 8 chunks each. No commit.
// ---------------------------------------------------------------------------
__device__ __forceinline__ void fill_tile(uint32_t sdst, int zrow, int tid) {
    const __nv_bfloat16* src = g_zh + ((size_t)zrow << 8);
    #pragma unroll
    for (int i = 0; i < 8; ++i) {
        int q = tid + (i << 9);          // 16B chunk id 0..4095
        int r = q >> 5;                  // row 0..127
        int c = q & 31;
        cp16(sdst + (r << 9) + ((c ^ (r & 7)) << 4), src + ((size_t)q << 3));
    }
}

// ---------------------------------------------------------------------------
// Kernel 2: persistent upper-tri sim-GEMM + exp-sum + fused final reduce.
// 148 CTAs x 512 threads; 16 warps = 4(M) x 4(N); warp tile 32x32.
// ---------------------------------------------------------------------------
__global__ __launch_bounds__(512, 1) void sim_kernel(float* __restrict__ out) {
    extern __shared__ char smem[];
    const uint32_t sb = smem_u32(smem);
    const uint32_t FULL[2]  = {sb + SM_BAR,      sb + SM_BAR + 8};
    const uint32_t EMPTY[2] = {sb + SM_BAR + 16, sb + SM_BAR + 24};
    const uint32_t BUF[2]   = {sb + SM_B0, sb + SM_B1};
    const int tid = threadIdx.x, wid = tid >> 5, lane = tid & 31;
    const int wm = wid >> 2, wn = wid & 3;   // 4 x 4 warp grid

    const int b = blockIdx.x, nb = gridDim.x;
    const int t0 = (b * TOTAL_UT) / nb;
    const int t1 = ((b + 1) * TOTAL_UT) / nb;
    const int nt = t1 - t0;

    int R = 0, rem = t0;
    while (rem >= NTILE - R) { rem -= NTILE - R; R++; }
    int C = R + rem;

    if (tid == 0) {
        MBAR_INIT(FULL[0], 512); MBAR_INIT(FULL[1], 512);
        MBAR_INIT(EMPTY[0], 512); MBAR_INIT(EMPTY[1], 512);
    }
    __syncthreads();

    // ldmatrix addressing (512B rows, chunk-XOR swizzle)
    const uint32_t rm  = (uint32_t)(lane & 7) << 4;
    const uint32_t hiA = (uint32_t)(lane >> 4) << 4;
    const uint32_t hiB = (uint32_t)((lane >> 3) & 1) << 4;
    uint32_t aRow[2];
    #pragma unroll
    for (int mf = 0; mf < 2; ++mf)
        aRow[mf] = (uint32_t)(wm * 32 + mf * 16 + (lane & 15)) << 9;
    const uint32_t rB0 = (uint32_t)(wn * 32 + (lane & 7) + ((lane >> 4) << 3));
    const uint32_t bRow0 = rB0 << 9, bRow1 = (rB0 + 16) << 9;

    float dacc[2][2];
    dacc[0][0] = dacc[0][1] = dacc[1][0] = dacc[1][1] = 0.f;

    int loadedR = R;
    fill_tile(sb + SM_A, R << 7, tid);
    fill_tile(BUF[0], C << 7, tid);
    CPA_NOINC(FULL[0]);
    CP_COMMIT(); CP_WAIT0();
    __syncthreads();

    for (int i = 0; i < nt; ++i) {
        int Rn = R, Cn = C + 1;
        if (Cn == NTILE) { Rn = R + 1; Cn = Rn; }

        if (R != loadedR) {              // rare: flush rows + reload A
            #pragma unroll
            for (int mf = 0; mf < 2; ++mf)
                #pragma unroll
                for (int h = 0; h < 2; ++h) {
                    float v = dacc[mf][h];
                    v += __shfl_xor_sync(~0u, v, 1);
                    v += __shfl_xor_sync(~0u, v, 2);
                    if ((lane & 3) == 0)
                        atomicAdd(&g_denom[(loadedR << 7) + wm * 32 + mf * 16
                                           + (lane >> 2) + h * 8], v);
                    dacc[mf][h] = 0.f;
                }
            __syncthreads();
            fill_tile(sb + SM_A, R << 7, tid);
            CP_COMMIT(); CP_WAIT0();
            __syncthreads();
            loadedR = R;
        }

        if (i + 1 < nt) {
            const int nbuf = (i + 1) & 1;
            if (i + 1 >= 2)
                MBAR_WAIT(EMPTY[nbuf], ((((i + 1) >> 1) - 1) & 1));
            fill_tile(BUF[nbuf], Cn << 7, tid);
            CPA_NOINC(FULL[nbuf]);
        }

        const int cb = i & 1;
        MBAR_WAIT(FULL[cb], (i >> 1) & 1);
        const uint32_t aBase = sb + SM_A;
        const uint32_t bBase = BUF[cb];

        float acc[2][4][4];
        #pragma unroll
        for (int x = 0; x < 2; x++)
            #pragma unroll
            for (int y = 0; y < 4; y++)
                #pragma unroll
                for (int c = 0; c < 4; c++) acc[x][y][c] = 0.f;

        #pragma unroll
        for (int s = 0; s < 16; ++s) {
            const uint32_t offA = (((uint32_t)s << 5) + hiA) ^ rm;
            const uint32_t offB = (((uint32_t)s << 5) + hiB) ^ rm;
            uint32_t a[2][4];
            #pragma unroll
            for (int mf = 0; mf < 2; ++mf)
                LDSM4(a[mf][0], a[mf][1], a[mf][2], a[mf][3],
                      aBase + aRow[mf] + offA);
            uint32_t bq[2][4];
            LDSM4(bq[0][0], bq[0][1], bq[0][2], bq[0][3], bBase + bRow0 + offB);
            LDSM4(bq[1][0], bq[1][1], bq[1][2], bq[1][3], bBase + bRow1 + offB);
            #pragma unroll
            for (int mf = 0; mf < 2; ++mf)
                #pragma unroll
                for (int nf = 0; nf < 4; ++nf)
                    MMA16816(acc[mf][nf], a[mf],
                             bq[nf >> 1][(nf & 1) * 2],
                             bq[nf >> 1][(nf & 1) * 2 + 1]);
        }
        MBAR_ARRIVE(EMPTY[cb]);

        // epilogue (overlaps other warps' MMA)
        const bool offDiag = (C != R);
        float colacc[4][2];
        #pragma unroll
        for (int x = 0; x < 4; x++) { colacc[x][0] = 0.f; colacc[x][1] = 0.f; }

        #pragma unroll
        for (int mf = 0; mf < 2; ++mf)
            #pragma unroll
            for (int nf = 0; nf < 4; ++nf)
                #pragma unroll
                for (int c = 0; c < 4; ++c) {
                    float e = ex2f(acc[mf][nf][c] * C2);
                    dacc[mf][c >> 1] += e;
                    colacc[nf][c & 1] += e;
                }

        if (offDiag) {
            #pragma unroll
            for (int nf = 0; nf < 4; ++nf)
                #pragma unroll
                for (int p = 0; p < 2; ++p) {
                    float v = colacc[nf][p];
                    v += __shfl_xor_sync(~0u, v, 4);
                    v += __shfl_xor_sync(~0u, v, 8);
                    v += __shfl_xor_sync(~0u, v, 16);
                    if (lane < 4)
                        atomicAdd(&g_denom[(C << 7) + wn * 32 + nf * 8
                                           + (lane & 3) * 2 + p], v);
                }
        }

        R = Rn; C = Cn;
    }

    // final row flush
    #pragma unroll
    for (int mf = 0; mf < 2; ++mf)
        #pragma unroll
        for (int h = 0; h < 2; ++h) {
            float v = dacc[mf][h];
            v += __shfl_xor_sync(~0u, v, 1);
            v += __shfl_xor_sync(~0u, v, 2);
            if ((lane & 3) == 0)
                atomicAdd(&g_denom[(loadedR << 7) + wm * 32 + mf * 16
                                   + (lane >> 2) + h * 8], v);
        }

    __syncthreads();
    if (tid == 0) {
        MBAR_INVAL(FULL[0]); MBAR_INVAL(FULL[1]);
        MBAR_INVAL(EMPTY[0]); MBAR_INVAL(EMPTY[1]);
    }

    // ---- fused finish: last CTA reduces the scalar ----
    __shared__ unsigned int amLast;
    if (tid == 0) {
        __threadfence();
        amLast = (atomicAdd(&g_done, 1u) == (unsigned)(nb - 1)) ? 1u : 0u;
    }
    __syncthreads();
    if (amLast) {
        __threadfence();
        double s = 0.0;
        for (int r = tid; r < NROW; r += 512) {
            float denom = g_denom[r] - ex2f(g_self[r] * C2);
            int pk = (r < NHALF) ? r : (r - NHALF);
            s += (double)(__logf(denom) - 2.0f * g_pos[pk]);
        }
        #pragma unroll
        for (int o = 16; o; o >>= 1) s += __shfl_xor_sync(~0u, s, o);
        __shared__ double ws[16];
        if (lane == 0) ws[wid] = s;
        __syncthreads();
        if (tid == 0) {
            double tot = 0.0;
            #pragma unroll
            for (int i = 0; i < 16; i++) tot += ws[i];
            out[0] = (float)(tot / (double)NROW);
        }
    }
}

// ---------------------------------------------------------------------------
extern "C" void kernel_launch(void* const* d_in, const int* in_sizes, int n_in,
                              void* d_out, int out_size) {
    const float* emb_i = (const float*)d_in[0];
    const float* emb_j = (const float*)d_in[1];
    float* out = (float*)d_out;

    cudaFuncSetAttribute(sim_kernel, cudaFuncAttributeMaxDynamicSharedMemorySize,
                         SMEM_TOTAL);
    norm_pos_kernel<<<1024, 256>>>(emb_i, emb_j);
    sim_kernel<<<NB, 512, SMEM_TOTAL>>>(out);
}